// round 3
// baseline (speedup 1.0000x reference)
#include <cuda_runtime.h>
#include <math.h>

#define S_LEN 1024
#define BATCH 2
#define DM    1024
#define NH    16
#define DH    64
#define CC    32
#define MROWS (S_LEN*BATCH)   /* 2048 */
#define QSCALE 0.125f         /* 1/sqrt(64) */

/* ------------------------------------------------------------------ */
/* Scratch: one big __device__ array (no allocation allowed).          */
/* Layout (floats):                                                    */
/*  [0)        q_u     2048x1024                                       */
/*  [2M)       k_d     2048x1024                                       */
/*  [4M)       v_d     2048x1024                                       */
/*  [6M)       v_d_k   2048x1024                                       */
/*  [8M)       v_d_v   2048x1024                                       */
/*  [10M)      att     2048x1024                                       */
/*  [12M)      down    [bh=32][c=32][s=1024]                           */
/*  [13M)      w       [bh=32][s=1024][c=32]                           */
/* ------------------------------------------------------------------ */
__device__ float g_scratch[14 * 1024 * 1024];

#define OFF_QU   ((size_t)0)
#define OFF_KD   ((size_t)2*1024*1024)
#define OFF_VD   ((size_t)4*1024*1024)
#define OFF_VDK  ((size_t)6*1024*1024)
#define OFF_VDV  ((size_t)8*1024*1024)
#define OFF_ATT  ((size_t)10*1024*1024)
#define OFF_DOWN ((size_t)12*1024*1024)
#define OFF_W    ((size_t)13*1024*1024)

/* ------------------------------------------------------------------ */
/* SGEMM NT + bias:  C[m,n] = sum_k A[m,k]*B[n,k] + bias[n]            */
/* 128x128 tile, kTile=8, 256 threads, 8x8 microtile.                  */
/* Requires M%128==0, N%128==0, K%8==0.                                */
/* ------------------------------------------------------------------ */
__global__ __launch_bounds__(256) void sgemm_nt_bias(
    const float* __restrict__ A, const float* __restrict__ B,
    const float* __restrict__ bias, float* __restrict__ C,
    int M, int N, int K)
{
    __shared__ float As[8][132];
    __shared__ float Bs[8][132];
    const int tid  = threadIdx.x;
    const int bm   = blockIdx.y * 128;
    const int bn   = blockIdx.x * 128;
    const int lrow = tid >> 1;            /* 0..127 */
    const int lcol = (tid & 1) << 2;      /* 0 or 4 */
    const int tx   = tid & 15;            /* col micro */
    const int ty   = tid >> 4;            /* row micro */

    const float* Ap = A + (size_t)(bm + lrow) * K + lcol;
    const float* Bp = B + (size_t)(bn + lrow) * K + lcol;

    float acc[8][8];
    #pragma unroll
    for (int i = 0; i < 8; i++)
        #pragma unroll
        for (int j = 0; j < 8; j++) acc[i][j] = 0.f;

    for (int k0 = 0; k0 < K; k0 += 8) {
        float4 av = *(const float4*)(Ap + k0);
        float4 bv = *(const float4*)(Bp + k0);
        __syncthreads();
        As[lcol+0][lrow] = av.x; As[lcol+1][lrow] = av.y;
        As[lcol+2][lrow] = av.z; As[lcol+3][lrow] = av.w;
        Bs[lcol+0][lrow] = bv.x; Bs[lcol+1][lrow] = bv.y;
        Bs[lcol+2][lrow] = bv.z; Bs[lcol+3][lrow] = bv.w;
        __syncthreads();
        #pragma unroll
        for (int k = 0; k < 8; k++) {
            float a[8], b[8];
            *(float4*)(a)   = *(const float4*)&As[k][ty*4];
            *(float4*)(a+4) = *(const float4*)&As[k][64 + ty*4];
            *(float4*)(b)   = *(const float4*)&Bs[k][tx*4];
            *(float4*)(b+4) = *(const float4*)&Bs[k][64 + tx*4];
            #pragma unroll
            for (int i = 0; i < 8; i++)
                #pragma unroll
                for (int j = 0; j < 8; j++)
                    acc[i][j] += a[i] * b[j];
        }
    }

    float bb[8];
    #pragma unroll
    for (int j = 0; j < 8; j++) {
        int col = bn + ((j < 4) ? tx*4 + j : 64 + tx*4 + (j - 4));
        bb[j] = bias[col];
    }
    #pragma unroll
    for (int i = 0; i < 8; i++) {
        int row = bm + ((i < 4) ? ty*4 + i : 64 + ty*4 + (i - 4));
        float4 v0 = make_float4(acc[i][0]+bb[0], acc[i][1]+bb[1],
                                acc[i][2]+bb[2], acc[i][3]+bb[3]);
        float4 v1 = make_float4(acc[i][4]+bb[4], acc[i][5]+bb[5],
                                acc[i][6]+bb[6], acc[i][7]+bb[7]);
        *(float4*)&C[(size_t)row * N + bn + tx*4]      = v0;
        *(float4*)&C[(size_t)row * N + bn + 64 + tx*4] = v1;
    }
}

/* ------------------------------------------------------------------ */
/* down[bh][c][s] = (q_down[c, h*64+:]*scale) . k_d[s,b,h*64+:]        */
/* grid (S/128, 32), block 128                                         */
/* ------------------------------------------------------------------ */
__global__ __launch_bounds__(128) void down_kernel(
    const float* __restrict__ q_down, const float* __restrict__ kd,
    float* __restrict__ down)
{
    const int bh = blockIdx.y;
    const int b  = bh >> 4;
    const int h  = bh & 15;
    const int s  = blockIdx.x * 128 + threadIdx.x;

    __shared__ float qd[CC][DH];
    for (int i = threadIdx.x; i < CC * DH; i += 128) {
        int c = i >> 6, d = i & 63;
        qd[c][d] = q_down[c * DM + h * DH + d] * QSCALE;
    }
    __syncthreads();

    const float* kp = kd + (size_t)s * (BATCH * DM) + b * DM + h * DH;
    float kr[DH];
    #pragma unroll
    for (int d = 0; d < DH; d++) kr[d] = kp[d];

    #pragma unroll 4
    for (int c = 0; c < CC; c++) {
        float acc = 0.f;
        #pragma unroll
        for (int d = 0; d < DH; d++) acc += qd[c][d] * kr[d];
        down[((size_t)bh * CC + c) * S_LEN + s] = acc;
    }
}

/* ------------------------------------------------------------------ */
/* Per (bh,c): global max over s, then w[bh][s][c] = exp(down - max).  */
/* grid 32*32 blocks, block 128                                        */
/* ------------------------------------------------------------------ */
__global__ __launch_bounds__(128) void maxexp_kernel(
    const float* __restrict__ down, float* __restrict__ wmat)
{
    const int bc = blockIdx.x;        /* bh*32 + c */
    const int bh = bc >> 5;
    const int c  = bc & 31;
    const int t  = threadIdx.x;
    const float* row = down + (size_t)bc * S_LEN;

    float mx = -3.0e38f;
    for (int i = t; i < S_LEN; i += 128) mx = fmaxf(mx, row[i]);

    __shared__ float red[128];
    red[t] = mx;
    __syncthreads();
    for (int st = 64; st > 0; st >>= 1) {
        if (t < st) red[t] = fmaxf(red[t], red[t + st]);
        __syncthreads();
    }
    mx = red[0];

    for (int i = t; i < S_LEN; i += 128)
        wmat[((size_t)bh * S_LEN + i) * CC + c] = __expf(row[i] - mx);
}

/* ------------------------------------------------------------------ */
/* Streaming compression attention.                                    */
/* One block per (b,h). 256 threads = 8 warps.                         */
/* lane = c (0..31); warp w owns d in [w*8, w*8+8).                    */
/* Per-thread state: A_k[8], A_v[8], norm (replicated per warp).       */
/* One __syncthreads per s-step (partial up exchange, double-buffered).*/
/* ------------------------------------------------------------------ */
#define CHNK 32
__global__ __launch_bounds__(256) void attn_kernel(
    const float* __restrict__ qu, const float* __restrict__ vk,
    const float* __restrict__ vv, const float* __restrict__ wmat,
    float* __restrict__ att)
{
    const int bh   = blockIdx.x;
    const int b    = bh >> 4;
    const int h    = bh & 15;
    const int tid  = threadIdx.x;
    const int lane = tid & 31;   /* c */
    const int warp = tid >> 5;   /* d-group */

    __shared__ float qs[CHNK][DH];
    __shared__ float vks[CHNK][DH];
    __shared__ float vvs[CHNK][DH];
    __shared__ float ws[CHNK][CC];
    __shared__ float part[2][8][32];

    float Ak[8], Av[8];
    #pragma unroll
    for (int j = 0; j < 8; j++) { Ak[j] = 0.f; Av[j] = 0.f; }
    float norm = 0.f;
    int buf = 0;

    const size_t base_off = (size_t)b * DM + h * DH;

    for (int s0 = 0; s0 < S_LEN; s0 += CHNK) {
        __syncthreads();                  /* protect smem tiles (WAR) */
        for (int i = tid; i < CHNK * DH; i += 256) {
            int r = i >> 6, d = i & 63;
            size_t g = (size_t)(s0 + r) * (BATCH * DM) + base_off + d;
            qs[r][d]  = qu[g] * QSCALE;
            vks[r][d] = vk[g];
            vvs[r][d] = vv[g];
        }
        for (int i = tid; i < CHNK * CC; i += 256) {
            int r = i >> 5, c = i & 31;
            ws[r][c] = wmat[((size_t)bh * S_LEN + s0 + r) * CC + c];
        }
        __syncthreads();

        for (int i = 0; i < CHNK; i++) {
            const float wvv = ws[i][lane];
            norm += wvv;
            float up_part = 0.f;
            #pragma unroll
            for (int j = 0; j < 8; j++) {
                Ak[j] += wvv * vks[i][warp*8 + j];
                Av[j] += wvv * vvs[i][warp*8 + j];
                up_part += qs[i][warp*8 + j] * Ak[j];
            }
            part[buf][warp][lane] = up_part;
            __syncthreads();

            float up = 0.f;
            #pragma unroll
            for (int ww = 0; ww < 8; ww++) up += part[buf][ww][lane];
            up /= norm;

            /* softmax over c == lanes: pure warp shuffles, replicated */
            float mx = up;
            #pragma unroll
            for (int off = 16; off > 0; off >>= 1)
                mx = fmaxf(mx, __shfl_xor_sync(0xFFFFFFFFu, mx, off));
            float e = __expf(up - mx);
            float se = e;
            #pragma unroll
            for (int off = 16; off > 0; off >>= 1)
                se += __shfl_xor_sync(0xFFFFFFFFu, se, off);
            const float coeff = e / (se * norm);

            /* out[d] = sum_c coeff_c * Av[c][d] : butterfly over lanes */
            float o[8];
            #pragma unroll
            for (int j = 0; j < 8; j++) o[j] = coeff * Av[j];
            #pragma unroll
            for (int off = 16; off > 0; off >>= 1)
                #pragma unroll
                for (int j = 0; j < 8; j++)
                    o[j] += __shfl_xor_sync(0xFFFFFFFFu, o[j], off);

            if (lane < 8)
                att[(size_t)(s0 + i) * (BATCH * DM) + base_off + warp*8 + lane] = o[lane];
            buf ^= 1;
        }
    }
}

/* ------------------------------------------------------------------ */
extern "C" void kernel_launch(void* const* d_in, const int* in_sizes, int n_in,
                              void* d_out, int out_size)
{
    (void)in_sizes; (void)n_in; (void)out_size;
    const float* x      = (const float*)d_in[0];
    const float* q_down = (const float*)d_in[1];
    const float* Wq     = (const float*)d_in[2];
    const float* bq     = (const float*)d_in[3];
    const float* Wk     = (const float*)d_in[4];
    const float* bk     = (const float*)d_in[5];
    const float* Wv     = (const float*)d_in[6];
    const float* bv     = (const float*)d_in[7];
    const float* Wo     = (const float*)d_in[8];
    const float* bo     = (const float*)d_in[9];
    float* out = (float*)d_out;

    float* scr = nullptr;
    cudaGetSymbolAddress((void**)&scr, g_scratch);
    float* g_qu  = scr + OFF_QU;
    float* g_kd  = scr + OFF_KD;
    float* g_vd  = scr + OFF_VD;
    float* g_vdk = scr + OFF_VDK;
    float* g_vdv = scr + OFF_VDV;
    float* g_att = scr + OFF_ATT;
    float* g_dn  = scr + OFF_DOWN;
    float* g_w   = scr + OFF_W;

    dim3 gg(DM / 128, MROWS / 128);   /* (8, 16) */
    dim3 gb(256);

    sgemm_nt_bias<<<gg, gb>>>(x, Wq, bq, g_qu, MROWS, DM, DM);
    sgemm_nt_bias<<<gg, gb>>>(x, Wk, bk, g_kd, MROWS, DM, DM);
    sgemm_nt_bias<<<gg, gb>>>(x, Wv, bv, g_vd, MROWS, DM, DM);
    sgemm_nt_bias<<<gg, gb>>>(g_vd, Wk, bk, g_vdk, MROWS, DM, DM);
    sgemm_nt_bias<<<gg, gb>>>(g_vd, Wv, bv, g_vdv, MROWS, DM, DM);

    down_kernel<<<dim3(S_LEN / 128, BATCH * NH), 128>>>(q_down, g_kd, g_dn);
    maxexp_kernel<<<BATCH * NH * CC, 128>>>(g_dn, g_w);

    attn_kernel<<<BATCH * NH, 256>>>(g_qu, g_vdk, g_vdv, g_w, g_att);

    sgemm_nt_bias<<<gg, gb>>>(g_att, Wo, bo, out, MROWS, DM, DM);
}

// round 8
// speedup vs baseline: 3.2011x; 3.2011x over previous
#include <cuda_runtime.h>
#include <cuda_bf16.h>
#include <math.h>
#include <stdint.h>

#define S_LEN 1024
#define BATCH 2
#define DM    1024
#define NH    16
#define DH    64
#define CC    32
#define MROWS (S_LEN*BATCH)   /* 2048 */
#define QSCALE 0.125f         /* 1/sqrt(64) */
#define NCH   16              /* chunks over S */
#define CS    64              /* chunk size    */

/* ------------------------------------------------------------------ */
/* Scratch (no allocation allowed). 17M floats = 68 MB.                */
/* ------------------------------------------------------------------ */
__device__ float g_scratch[17 * 1024 * 1024];

#define OFF_QU   ((size_t)0)
#define OFF_KD   ((size_t)2*1024*1024)
#define OFF_VD   ((size_t)4*1024*1024)
#define OFF_VDK  ((size_t)6*1024*1024)
#define OFF_VDV  ((size_t)8*1024*1024)
#define OFF_ATT  ((size_t)10*1024*1024)
#define OFF_DOWN ((size_t)12*1024*1024)
#define OFF_W    ((size_t)13*1024*1024)
#define OFF_STK  ((size_t)14*1024*1024)   /* [bh][ch][c][d]  1M */
#define OFF_STV  ((size_t)15*1024*1024)   /* [bh][ch][c][d]  1M */
#define OFF_STN  ((size_t)16*1024*1024)   /* [bh][ch][c]    16K */

/* ================================================================== */
/* helpers                                                             */
/* ================================================================== */
__device__ __forceinline__ uint32_t smem_addr_u32(const void* p) {
    uint32_t a;
    asm("{ .reg .u64 t; cvta.to.shared.u64 t, %1; cvt.u32.u64 %0, t; }"
        : "=r"(a) : "l"(p));
    return a;
}

#define LDM4(r, addr)                                                         \
    asm volatile("ldmatrix.sync.aligned.m8n8.x4.shared.b16 {%0,%1,%2,%3}, [%4];" \
        : "=r"((r)[0]), "=r"((r)[1]), "=r"((r)[2]), "=r"((r)[3])              \
        : "r"(addr))

#define MMA16816(d, a, b0, b1)                                                \
    asm volatile(                                                             \
        "mma.sync.aligned.m16n8k16.row.col.f32.bf16.bf16.f32 "                \
        "{%0,%1,%2,%3}, {%4,%5,%6,%7}, {%8,%9}, {%0,%1,%2,%3};"               \
        : "+f"((d)[0]), "+f"((d)[1]), "+f"((d)[2]), "+f"((d)[3])              \
        : "r"((a)[0]), "r"((a)[1]), "r"((a)[2]), "r"((a)[3]),                 \
          "r"(b0), "r"(b1))

__device__ __forceinline__ uint32_t pack_bf16(float x, float y) {
    __nv_bfloat16 a = __float2bfloat16(x), b = __float2bfloat16(y);
    return (uint32_t)__bfloat16_as_ushort(a) |
           ((uint32_t)__bfloat16_as_ushort(b) << 16);
}

/* float4 -> hi bf16x2 pair + lo (residual) bf16x2 pair */
__device__ __forceinline__ void cvt_split(const float4 v,
    uint32_t& h0, uint32_t& h1, uint32_t& l0, uint32_t& l1)
{
    __nv_bfloat16 a = __float2bfloat16(v.x), b = __float2bfloat16(v.y),
                  c = __float2bfloat16(v.z), d = __float2bfloat16(v.w);
    h0 = (uint32_t)__bfloat16_as_ushort(a) | ((uint32_t)__bfloat16_as_ushort(b) << 16);
    h1 = (uint32_t)__bfloat16_as_ushort(c) | ((uint32_t)__bfloat16_as_ushort(d) << 16);
    l0 = pack_bf16(v.x - __bfloat162float(a), v.y - __bfloat162float(b));
    l1 = pack_bf16(v.z - __bfloat162float(c), v.w - __bfloat162float(d));
}

/* ================================================================== */
/* HMMA GEMM NT + bias: C[2048,1024] = A[2048,1024]·B[1024,1024]^T     */
/* bf16 hi/lo split (3 products ~ fp32). 128x128 tile, 8 warps 64x32.  */
/* K-tile 32, double-buffered, pad-40 rows (conflict-free ldmatrix).   */
/* ================================================================== */
#define TPAD 40                    /* halfs per smem row */
#define TILE_B (128*TPAD*2)        /* 10240 bytes per matrix tile */
#define STG_B  (4*TILE_B)          /* Ah,Al,Bh,Bl = 40960 */
#define GEMM_SMEM (2*STG_B)        /* 81920 */

__global__ __launch_bounds__(256, 1) void gemm_mma_bias(
    const float* __restrict__ A, const float* __restrict__ B,
    const float* __restrict__ bias, float* __restrict__ C)
{
    extern __shared__ __align__(16) char sm[];
    const uint32_t sbase = smem_addr_u32(sm);
    const int tid = threadIdx.x, lane = tid & 31, w = tid >> 5;
    const int wm = w & 1, wn = w >> 1;
    const int bm = blockIdx.y * 128, bn = blockIdx.x * 128;

    float acc[4][4][4];
    #pragma unroll
    for (int i = 0; i < 4; i++)
        #pragma unroll
        for (int j = 0; j < 4; j++)
            #pragma unroll
            for (int k = 0; k < 4; k++) acc[i][j][k] = 0.f;

    /* global staging: thread loads half a row of A tile + half a row of B */
    const float* Ap = A + (size_t)(bm + (tid >> 1)) * DM + (tid & 1) * 16;
    const float* Bp = B + (size_t)(bn + (tid >> 1)) * DM + (tid & 1) * 16;
    const uint32_t stRow = (uint32_t)((tid >> 1) * (TPAD * 2) + (tid & 1) * 32);

    /* ldmatrix per-thread relative offsets */
    const uint32_t aRel = (uint32_t)(((wm * 64 + (lane & 15)) * TPAD
                                      + (lane >> 4) * 8) * 2);
    const uint32_t bRel = (uint32_t)(((wn * 32 + (lane & 7) + ((lane >> 4) & 1) * 8) * TPAD
                                      + ((lane >> 3) & 1) * 8) * 2);

    float4 ra[4], rb[4];

    /* prologue: load + store stage 0 */
    #pragma unroll
    for (int i = 0; i < 4; i++) {
        ra[i] = *(const float4*)(Ap + i * 4);
        rb[i] = *(const float4*)(Bp + i * 4);
    }
    {
        const uint32_t so = sbase;
        #pragma unroll
        for (int i = 0; i < 4; i++) {
            uint32_t h0, h1, l0, l1;
            cvt_split(ra[i], h0, h1, l0, l1);
            asm volatile("st.shared.v2.b32 [%0], {%1,%2};"
                :: "r"(so + stRow + i * 8), "r"(h0), "r"(h1) : "memory");
            asm volatile("st.shared.v2.b32 [%0], {%1,%2};"
                :: "r"(so + TILE_B + stRow + i * 8), "r"(l0), "r"(l1) : "memory");
            cvt_split(rb[i], h0, h1, l0, l1);
            asm volatile("st.shared.v2.b32 [%0], {%1,%2};"
                :: "r"(so + 2*TILE_B + stRow + i * 8), "r"(h0), "r"(h1) : "memory");
            asm volatile("st.shared.v2.b32 [%0], {%1,%2};"
                :: "r"(so + 3*TILE_B + stRow + i * 8), "r"(l0), "r"(l1) : "memory");
        }
    }
    __syncthreads();

    for (int kt = 0; kt < 32; ++kt) {
        if (kt < 31) {
            #pragma unroll
            for (int i = 0; i < 4; i++) {
                ra[i] = *(const float4*)(Ap + (kt + 1) * 32 + i * 4);
                rb[i] = *(const float4*)(Bp + (kt + 1) * 32 + i * 4);
            }
        }
        const uint32_t so = sbase + (uint32_t)(kt & 1) * STG_B;

        #pragma unroll
        for (int ks = 0; ks < 2; ++ks) {
            uint32_t ah[4][4], al[4][4], bh[2][4], bl[2][4];
            #pragma unroll
            for (int mt = 0; mt < 4; mt++) {
                uint32_t off = aRel + (uint32_t)(mt * 16 * TPAD * 2 + ks * 32);
                LDM4(ah[mt], so + off);
                LDM4(al[mt], so + TILE_B + off);
            }
            #pragma unroll
            for (int g = 0; g < 2; g++) {
                uint32_t off = bRel + (uint32_t)(g * 16 * TPAD * 2 + ks * 32);
                LDM4(bh[g], so + 2*TILE_B + off);
                LDM4(bl[g], so + 3*TILE_B + off);
            }
            #pragma unroll
            for (int mt = 0; mt < 4; mt++)
                #pragma unroll
                for (int nt = 0; nt < 4; nt++) {
                    const int g = nt >> 1, p = (nt & 1) * 2;
                    MMA16816(acc[mt][nt], ah[mt], bh[g][p], bh[g][p + 1]);
                    MMA16816(acc[mt][nt], al[mt], bh[g][p], bh[g][p + 1]);
                    MMA16816(acc[mt][nt], ah[mt], bl[g][p], bl[g][p + 1]);
                }
        }

        if (kt < 31) {
            const uint32_t sd = sbase + (uint32_t)((kt + 1) & 1) * STG_B;
            #pragma unroll
            for (int i = 0; i < 4; i++) {
                uint32_t h0, h1, l0, l1;
                cvt_split(ra[i], h0, h1, l0, l1);
                asm volatile("st.shared.v2.b32 [%0], {%1,%2};"
                    :: "r"(sd + stRow + i * 8), "r"(h0), "r"(h1) : "memory");
                asm volatile("st.shared.v2.b32 [%0], {%1,%2};"
                    :: "r"(sd + TILE_B + stRow + i * 8), "r"(l0), "r"(l1) : "memory");
                cvt_split(rb[i], h0, h1, l0, l1);
                asm volatile("st.shared.v2.b32 [%0], {%1,%2};"
                    :: "r"(sd + 2*TILE_B + stRow + i * 8), "r"(h0), "r"(h1) : "memory");
                asm volatile("st.shared.v2.b32 [%0], {%1,%2};"
                    :: "r"(sd + 3*TILE_B + stRow + i * 8), "r"(l0), "r"(l1) : "memory");
            }
        }
        __syncthreads();
    }

    /* epilogue */
    #pragma unroll
    for (int mt = 0; mt < 4; mt++) {
        const int r0 = bm + wm * 64 + mt * 16 + (lane >> 2);
        #pragma unroll
        for (int nt = 0; nt < 4; nt++) {
            const int c0 = bn + wn * 32 + nt * 8 + (lane & 3) * 2;
            const float b0 = bias[c0], b1 = bias[c0 + 1];
            float2 o0 = make_float2(acc[mt][nt][0] + b0, acc[mt][nt][1] + b1);
            float2 o1 = make_float2(acc[mt][nt][2] + b0, acc[mt][nt][3] + b1);
            *(float2*)&C[(size_t)r0 * DM + c0]       = o0;
            *(float2*)&C[(size_t)(r0 + 8) * DM + c0] = o1;
        }
    }
}

/* ------------------------------------------------------------------ */
/* down[bh][c][s] = (q_down[c, h*64+:]*scale) . k_d[s,b,h*64+:]        */
/* ------------------------------------------------------------------ */
__global__ __launch_bounds__(128) void down_kernel(
    const float* __restrict__ q_down, const float* __restrict__ kd,
    float* __restrict__ down)
{
    const int bh = blockIdx.y;
    const int b  = bh >> 4;
    const int h  = bh & 15;
    const int s  = blockIdx.x * 128 + threadIdx.x;

    __shared__ float qd[CC][DH];
    for (int i = threadIdx.x; i < CC * DH; i += 128) {
        int c = i >> 6, d = i & 63;
        qd[c][d] = q_down[c * DM + h * DH + d] * QSCALE;
    }
    __syncthreads();

    const float* kp = kd + (size_t)s * (BATCH * DM) + b * DM + h * DH;
    float kr[DH];
    #pragma unroll
    for (int d = 0; d < DH; d++) kr[d] = kp[d];

    #pragma unroll 4
    for (int c = 0; c < CC; c++) {
        float acc = 0.f;
        #pragma unroll
        for (int d = 0; d < DH; d++) acc += qd[c][d] * kr[d];
        down[((size_t)bh * CC + c) * S_LEN + s] = acc;
    }
}

/* ------------------------------------------------------------------ */
/* Per (bh,c): global max over s, then w[bh][s][c] = exp(down - max).  */
/* ------------------------------------------------------------------ */
__global__ __launch_bounds__(128) void maxexp_kernel(
    const float* __restrict__ down, float* __restrict__ wmat)
{
    const int bc = blockIdx.x;        /* bh*32 + c */
    const int bh = bc >> 5;
    const int c  = bc & 31;
    const int t  = threadIdx.x;
    const float* row = down + (size_t)bc * S_LEN;

    float mx = -3.0e38f;
    for (int i = t; i < S_LEN; i += 128) mx = fmaxf(mx, row[i]);

    __shared__ float red[128];
    red[t] = mx;
    __syncthreads();
    for (int st = 64; st > 0; st >>= 1) {
        if (t < st) red[t] = fmaxf(red[t], red[t + st]);
        __syncthreads();
    }
    mx = red[0];

    for (int i = t; i < S_LEN; i += 128)
        wmat[((size_t)bh * S_LEN + i) * CC + c] = __expf(row[i] - mx);
}

/* ------------------------------------------------------------------ */
/* P1: per-(bh,chunk) totals Tk/Tv/Tn over the chunk (no serial dep).  */
/* grid 32*16, block 256. lane=c, warp=d-octet.                        */
/* ------------------------------------------------------------------ */
__global__ __launch_bounds__(256) void chunk_sum_kernel(
    const float* __restrict__ vk, const float* __restrict__ vv,
    const float* __restrict__ wmat,
    float* __restrict__ stK, float* __restrict__ stV, float* __restrict__ stN)
{
    const int bc = blockIdx.x;
    const int bh = bc >> 4, ch = bc & 15;
    const int b  = bh >> 4, h = bh & 15;
    const int tid = threadIdx.x, lane = tid & 31, warp = tid >> 5;

    __shared__ float vks[32][DH];
    __shared__ float vvs[32][DH];
    __shared__ float ws[32][CC];

    float Ak[8], Av[8];
    #pragma unroll
    for (int j = 0; j < 8; j++) { Ak[j] = 0.f; Av[j] = 0.f; }
    float norm = 0.f;
    const size_t base_off = (size_t)b * DM + h * DH;

    for (int sub = 0; sub < 2; sub++) {
        const int s0 = ch * CS + sub * 32;
        __syncthreads();
        for (int i = tid; i < 32 * DH; i += 256) {
            int r = i >> 6, d = i & 63;
            size_t g = (size_t)(s0 + r) * (BATCH * DM) + base_off + d;
            vks[r][d] = vk[g];
            vvs[r][d] = vv[g];
        }
        for (int i = tid; i < 32 * CC; i += 256) {
            int r = i >> 5, c = i & 31;
            ws[r][c] = wmat[((size_t)bh * S_LEN + s0 + r) * CC + c];
        }
        __syncthreads();
        for (int i = 0; i < 32; i++) {
            const float wvv = ws[i][lane];
            norm += wvv;
            #pragma unroll
            for (int j = 0; j < 8; j++) {
                Ak[j] += wvv * vks[i][warp * 8 + j];
                Av[j] += wvv * vvs[i][warp * 8 + j];
            }
        }
    }

    const size_t so = ((size_t)bh * NCH + ch) * 2048 + lane * 64 + warp * 8;
    #pragma unroll
    for (int j = 0; j < 8; j++) { stK[so + j] = Ak[j]; stV[so + j] = Av[j]; }
    if (warp == 0) stN[((size_t)bh * NCH + ch) * 32 + lane] = norm;
}

/* ------------------------------------------------------------------ */
/* P2: in-place exclusive scan over chunks. grid 32, block 256.        */
/* ------------------------------------------------------------------ */
__global__ __launch_bounds__(256) void scan_kernel(
    float* __restrict__ stK, float* __restrict__ stV, float* __restrict__ stN)
{
    const int bh = blockIdx.x, tid = threadIdx.x;
    float* bK = stK + (size_t)bh * NCH * 2048;
    float* bV = stV + (size_t)bh * NCH * 2048;
    for (int idx = tid; idx < 2048; idx += 256) {
        float a = 0.f;
        #pragma unroll
        for (int j = 0; j < NCH; j++) {
            float t = bK[j * 2048 + idx]; bK[j * 2048 + idx] = a; a += t;
        }
        a = 0.f;
        #pragma unroll
        for (int j = 0; j < NCH; j++) {
            float t = bV[j * 2048 + idx]; bV[j * 2048 + idx] = a; a += t;
        }
    }
    if (tid < 32) {
        float* bN = stN + (size_t)bh * NCH * 32;
        float a = 0.f;
        #pragma unroll
        for (int j = 0; j < NCH; j++) {
            float t = bN[j * 32 + tid]; bN[j * 32 + tid] = a; a += t;
        }
    }
}

/* ------------------------------------------------------------------ */
/* P3: per-(bh,chunk) replay with outputs, starting from scanned state */
/* ------------------------------------------------------------------ */
__global__ __launch_bounds__(256) void attn_out_kernel(
    const float* __restrict__ qu, const float* __restrict__ vk,
    const float* __restrict__ vv, const float* __restrict__ wmat,
    const float* __restrict__ stK, const float* __restrict__ stV,
    const float* __restrict__ stN, float* __restrict__ att)
{
    const int bc = blockIdx.x;
    const int bh = bc >> 4, ch = bc & 15;
    const int b  = bh >> 4, h = bh & 15;
    const int tid = threadIdx.x, lane = tid & 31, warp = tid >> 5;

    __shared__ float qs[32][DH];
    __shared__ float vks[32][DH];
    __shared__ float vvs[32][DH];
    __shared__ float ws[32][CC];
    __shared__ float part[2][8][32];

    const size_t so = ((size_t)bh * NCH + ch) * 2048 + lane * 64 + warp * 8;
    float Ak[8], Av[8];
    #pragma unroll
    for (int j = 0; j < 8; j++) { Ak[j] = stK[so + j]; Av[j] = stV[so + j]; }
    float norm = stN[((size_t)bh * NCH + ch) * 32 + lane];
    int buf = 0;

    const size_t base_off = (size_t)b * DM + h * DH;

    for (int sub = 0; sub < 2; sub++) {
        const int s0 = ch * CS + sub * 32;
        __syncthreads();
        for (int i = tid; i < 32 * DH; i += 256) {
            int r = i >> 6, d = i & 63;
            size_t g = (size_t)(s0 + r) * (BATCH * DM) + base_off + d;
            qs[r][d]  = qu[g] * QSCALE;
            vks[r][d] = vk[g];
            vvs[r][d] = vv[g];
        }
        for (int i = tid; i < 32 * CC; i += 256) {
            int r = i >> 5, c = i & 31;
            ws[r][c] = wmat[((size_t)bh * S_LEN + s0 + r) * CC + c];
        }
        __syncthreads();

        for (int i = 0; i < 32; i++) {
            const float wvv = ws[i][lane];
            norm += wvv;
            float up_part = 0.f;
            #pragma unroll
            for (int j = 0; j < 8; j++) {
                Ak[j] += wvv * vks[i][warp * 8 + j];
                Av[j] += wvv * vvs[i][warp * 8 + j];
                up_part += qs[i][warp * 8 + j] * Ak[j];
            }
            part[buf][warp][lane] = up_part;
            __syncthreads();

            float up = 0.f;
            #pragma unroll
            for (int ww = 0; ww < 8; ww++) up += part[buf][ww][lane];
            up /= norm;

            float mx = up;
            #pragma unroll
            for (int off = 16; off > 0; off >>= 1)
                mx = fmaxf(mx, __shfl_xor_sync(0xFFFFFFFFu, mx, off));
            float e = __expf(up - mx);
            float se = e;
            #pragma unroll
            for (int off = 16; off > 0; off >>= 1)
                se += __shfl_xor_sync(0xFFFFFFFFu, se, off);
            const float coeff = e / (se * norm);

            float o[8];
            #pragma unroll
            for (int j = 0; j < 8; j++) o[j] = coeff * Av[j];
            #pragma unroll
            for (int off = 16; off > 0; off >>= 1)
                #pragma unroll
                for (int j = 0; j < 8; j++)
                    o[j] += __shfl_xor_sync(0xFFFFFFFFu, o[j], off);

            if (lane < 8)
                att[(size_t)(s0 + i) * (BATCH * DM) + base_off + warp * 8 + lane] = o[lane];
            buf ^= 1;
        }
    }
}

/* ------------------------------------------------------------------ */
extern "C" void kernel_launch(void* const* d_in, const int* in_sizes, int n_in,
                              void* d_out, int out_size)
{
    (void)in_sizes; (void)n_in; (void)out_size;
    const float* x      = (const float*)d_in[0];
    const float* q_down = (const float*)d_in[1];
    const float* Wq     = (const float*)d_in[2];
    const float* bq     = (const float*)d_in[3];
    const float* Wk     = (const float*)d_in[4];
    const float* bk     = (const float*)d_in[5];
    const float* Wv     = (const float*)d_in[6];
    const float* bv     = (const float*)d_in[7];
    const float* Wo     = (const float*)d_in[8];
    const float* bo     = (const float*)d_in[9];
    float* out = (float*)d_out;

    float* scr = nullptr;
    cudaGetSymbolAddress((void**)&scr, g_scratch);
    float* g_qu  = scr + OFF_QU;
    float* g_kd  = scr + OFF_KD;
    float* g_vd  = scr + OFF_VD;
    float* g_vdk = scr + OFF_VDK;
    float* g_vdv = scr + OFF_VDV;
    float* g_att = scr + OFF_ATT;
    float* g_dn  = scr + OFF_DOWN;
    float* g_w   = scr + OFF_W;
    float* g_stk = scr + OFF_STK;
    float* g_stv = scr + OFF_STV;
    float* g_stn = scr + OFF_STN;

    cudaFuncSetAttribute(gemm_mma_bias,
                         cudaFuncAttributeMaxDynamicSharedMemorySize, GEMM_SMEM);

    dim3 gg(DM / 128, MROWS / 128);   /* (8, 16) */

    gemm_mma_bias<<<gg, 256, GEMM_SMEM>>>(x,     Wq, bq, g_qu);
    gemm_mma_bias<<<gg, 256, GEMM_SMEM>>>(x,     Wk, bk, g_kd);
    gemm_mma_bias<<<gg, 256, GEMM_SMEM>>>(x,     Wv, bv, g_vd);
    gemm_mma_bias<<<gg, 256, GEMM_SMEM>>>(g_vd,  Wk, bk, g_vdk);
    gemm_mma_bias<<<gg, 256, GEMM_SMEM>>>(g_vd,  Wv, bv, g_vdv);

    down_kernel<<<dim3(S_LEN / 128, BATCH * NH), 128>>>(q_down, g_kd, g_dn);
    maxexp_kernel<<<BATCH * NH * CC, 128>>>(g_dn, g_w);

    chunk_sum_kernel<<<BATCH * NH * NCH, 256>>>(g_vdk, g_vdv, g_w,
                                                g_stk, g_stv, g_stn);
    scan_kernel<<<BATCH * NH, 256>>>(g_stk, g_stv, g_stn);
    attn_out_kernel<<<BATCH * NH * NCH, 256>>>(g_qu, g_vdk, g_vdv, g_w,
                                               g_stk, g_stv, g_stn, g_att);

    gemm_mma_bias<<<gg, 256, GEMM_SMEM>>>(g_att, Wo, bo, out);
}

// round 10
// speedup vs baseline: 3.2417x; 1.0127x over previous
#include <cuda_runtime.h>
#include <cuda_bf16.h>
#include <math.h>
#include <stdint.h>

#define S_LEN 1024
#define BATCH 2
#define DM    1024
#define NH    16
#define DH    64
#define CC    32
#define MROWS (S_LEN*BATCH)   /* 2048 */
#define QSCALE 0.125f
#define NCH   16
#define CS    64

/* ------------------------------------------------------------------ */
/* Scratch: 27M floats = 108 MB.                                       */
/* ------------------------------------------------------------------ */
__device__ float g_scratch[27 * 1024 * 1024];

#define MB (1024*1024)
#define OFF_QU   ((size_t)0)
#define OFF_KD   ((size_t)2*MB)
#define OFF_VD   ((size_t)4*MB)
#define OFF_VDK  ((size_t)6*MB)
#define OFF_VDV  ((size_t)8*MB)
#define OFF_ATT  ((size_t)10*MB)
#define OFF_DOWN ((size_t)12*MB)
#define OFF_W    ((size_t)13*MB)
#define OFF_STK  ((size_t)14*MB)
#define OFF_STV  ((size_t)15*MB)
#define OFF_STN  ((size_t)16*MB)
/* bf16 planes (sizes in floats; halfs = 2x) */
#define OFF_XH   ((size_t)17*MB)
#define OFF_XL   ((size_t)18*MB)
#define OFF_WQH  ((size_t)19*MB)
#define OFF_WQL  ((size_t)(19*MB+MB/2))
#define OFF_WKH  ((size_t)20*MB)
#define OFF_WKL  ((size_t)(20*MB+MB/2))
#define OFF_WVH  ((size_t)21*MB)
#define OFF_WVL  ((size_t)(21*MB+MB/2))
#define OFF_WOH  ((size_t)22*MB)
#define OFF_WOL  ((size_t)(22*MB+MB/2))
#define OFF_VDH  ((size_t)23*MB)
#define OFF_VDL  ((size_t)24*MB)
#define OFF_ATH  ((size_t)25*MB)
#define OFF_ATL  ((size_t)26*MB)

/* ================================================================== */
/* helpers                                                             */
/* ================================================================== */
__device__ __forceinline__ uint32_t smem_addr_u32(const void* p) {
    uint32_t a;
    asm("{ .reg .u64 t; cvta.to.shared.u64 t, %1; cvt.u32.u64 %0, t; }"
        : "=r"(a) : "l"(p));
    return a;
}

#define LDM4(r, addr)                                                         \
    asm volatile("ldmatrix.sync.aligned.m8n8.x4.shared.b16 {%0,%1,%2,%3}, [%4];" \
        : "=r"((r)[0]), "=r"((r)[1]), "=r"((r)[2]), "=r"((r)[3])              \
        : "r"(addr))

#define MMA16816(d, a, b0, b1)                                                \
    asm volatile(                                                             \
        "mma.sync.aligned.m16n8k16.row.col.f32.bf16.bf16.f32 "                \
        "{%0,%1,%2,%3}, {%4,%5,%6,%7}, {%8,%9}, {%0,%1,%2,%3};"               \
        : "+f"((d)[0]), "+f"((d)[1]), "+f"((d)[2]), "+f"((d)[3])              \
        : "r"((a)[0]), "r"((a)[1]), "r"((a)[2]), "r"((a)[3]),                 \
          "r"(b0), "r"(b1))

#define CP16(dst, src)                                                        \
    asm volatile("cp.async.cg.shared.global [%0], [%1], 16;"                  \
        :: "r"(dst), "l"((size_t)__cvta_generic_to_global(src)) : "memory")
#define CP_COMMIT() asm volatile("cp.async.commit_group;" ::: "memory")
#define CP_WAIT2()  asm volatile("cp.async.wait_group 2;"  ::: "memory")

__device__ __forceinline__ uint32_t pack_bf16(float x, float y) {
    __nv_bfloat16 a = __float2bfloat16(x), b = __float2bfloat16(y);
    return (uint32_t)__bfloat16_as_ushort(a) |
           ((uint32_t)__bfloat16_as_ushort(b) << 16);
}

/* ================================================================== */
/* fp32 -> (hi, lo) bf16 planes                                        */
/* ================================================================== */
__global__ __launch_bounds__(256) void cvt_split_kernel(
    const float4* __restrict__ src, uint2* __restrict__ hi,
    uint2* __restrict__ lo, int n4)
{
    int i = blockIdx.x * 256 + threadIdx.x;
    if (i >= n4) return;
    float4 v = src[i];
    __nv_bfloat16 a = __float2bfloat16(v.x), b = __float2bfloat16(v.y),
                  c = __float2bfloat16(v.z), d = __float2bfloat16(v.w);
    uint2 h, l;
    h.x = (uint32_t)__bfloat16_as_ushort(a) | ((uint32_t)__bfloat16_as_ushort(b) << 16);
    h.y = (uint32_t)__bfloat16_as_ushort(c) | ((uint32_t)__bfloat16_as_ushort(d) << 16);
    l.x = pack_bf16(v.x - __bfloat162float(a), v.y - __bfloat162float(b));
    l.y = pack_bf16(v.z - __bfloat162float(c), v.w - __bfloat162float(d));
    hi[i] = h;
    lo[i] = l;
}

/* ================================================================== */
/* HMMA GEMM NT + bias, bf16 hi/lo inputs, cp.async 4-stage pipeline.  */
/* C[z][2048,1024] = A[2048,1024]·B[z][1024,1024]^T + bias[z]          */
/* 128x128 tile, 8 warps (64x32), K-tile 32 halfs, row stride 80 B.    */
/* ================================================================== */
#define RS      80                 /* smem row stride bytes */
#define PART_B  (128*RS)           /* 10240 per matrix part */
#define STG_B   (4*PART_B)         /* Ah,Al,Bh,Bl = 40960   */
#define NSTAGE  4
#define GEMM_SMEM (NSTAGE*STG_B)   /* 163840 */

struct GemmArgs {
    const __nv_bfloat16* Bh;
    const __nv_bfloat16* Bl;
    const float*         bias;
    float*               C;
};

__device__ __forceinline__ void issue_stage(
    uint32_t sdst, const __nv_bfloat16* Ah, const __nv_bfloat16* Al,
    const __nv_bfloat16* Bh, const __nv_bfloat16* Bl,
    int bm, int bn, int k0, int tid)
{
    #pragma unroll
    for (int i = 0; i < 2; i++) {
        const int chunk = tid * 2 + i;
        const int r = chunk >> 2, seg = chunk & 3;
        const size_t ga = (size_t)(bm + r) * DM + k0 + seg * 8;
        const size_t gb = (size_t)(bn + r) * DM + k0 + seg * 8;
        const uint32_t d = sdst + (uint32_t)(r * RS + seg * 16);
        CP16(d,              Ah + ga);
        CP16(d + PART_B,     Al + ga);
        CP16(d + 2*PART_B,   Bh + gb);
        CP16(d + 3*PART_B,   Bl + gb);
    }
}

__global__ __launch_bounds__(256, 1) void gemm_bf16_bias(
    const __nv_bfloat16* __restrict__ Ah, const __nv_bfloat16* __restrict__ Al,
    GemmArgs a0, GemmArgs a1, GemmArgs a2)
{
    extern __shared__ __align__(16) char sm[];
    const uint32_t sbase = smem_addr_u32(sm);
    const int tid = threadIdx.x, lane = tid & 31, w = tid >> 5;
    const int wm = w & 1, wn = w >> 1;
    const int bm = blockIdx.y * 128, bn = blockIdx.x * 128;
    const GemmArgs ar = (blockIdx.z == 0) ? a0 : (blockIdx.z == 1) ? a1 : a2;
    const __nv_bfloat16* Bh = ar.Bh;
    const __nv_bfloat16* Bl = ar.Bl;

    float acc[4][4][4];
    #pragma unroll
    for (int i = 0; i < 4; i++)
        #pragma unroll
        for (int j = 0; j < 4; j++)
            #pragma unroll
            for (int k = 0; k < 4; k++) acc[i][j][k] = 0.f;

    const uint32_t aRel = (uint32_t)((wm * 64 + (lane & 15)) * RS + (lane >> 4) * 16);
    const uint32_t bRel = (uint32_t)((wn * 32 + (lane & 7) + ((lane >> 4) & 1) * 8) * RS
                                     + ((lane >> 3) & 1) * 16);

    /* prologue: stages 0..2 */
    #pragma unroll
    for (int s = 0; s < 3; s++) {
        issue_stage(sbase + s * STG_B, Ah, Al, Bh, Bl, bm, bn, s * 32, tid);
        CP_COMMIT();
    }

    for (int kt = 0; kt < 32; ++kt) {
        CP_WAIT2();
        __syncthreads();

        if (kt + 3 < 32)
            issue_stage(sbase + ((kt + 3) & 3) * STG_B, Ah, Al, Bh, Bl,
                        bm, bn, (kt + 3) * 32, tid);
        CP_COMMIT();   /* empty group when no issue: keeps wait_group 2 exact */

        const uint32_t so = sbase + (uint32_t)(kt & 3) * STG_B;
        #pragma unroll
        for (int ks = 0; ks < 2; ++ks) {
            uint32_t ah[4][4], al[4][4], bh[2][4], bl[2][4];
            #pragma unroll
            for (int mt = 0; mt < 4; mt++) {
                const uint32_t off = aRel + (uint32_t)(mt * 16 * RS + ks * 32);
                LDM4(ah[mt], so + off);
                LDM4(al[mt], so + PART_B + off);
            }
            #pragma unroll
            for (int g = 0; g < 2; g++) {
                const uint32_t off = bRel + (uint32_t)(g * 16 * RS + ks * 32);
                LDM4(bh[g], so + 2*PART_B + off);
                LDM4(bl[g], so + 3*PART_B + off);
            }
            #pragma unroll
            for (int mt = 0; mt < 4; mt++)
                #pragma unroll
                for (int nt = 0; nt < 4; nt++) {
                    const int g = nt >> 1, p = (nt & 1) * 2;
                    MMA16816(acc[mt][nt], ah[mt], bh[g][p], bh[g][p + 1]);
                    MMA16816(acc[mt][nt], al[mt], bh[g][p], bh[g][p + 1]);
                    MMA16816(acc[mt][nt], ah[mt], bl[g][p], bl[g][p + 1]);
                }
        }
    }

    /* epilogue */
    float* C = ar.C;
    const float* bias = ar.bias;
    #pragma unroll
    for (int mt = 0; mt < 4; mt++) {
        const int r0 = bm + wm * 64 + mt * 16 + (lane >> 2);
        #pragma unroll
        for (int nt = 0; nt < 4; nt++) {
            const int c0 = bn + wn * 32 + nt * 8 + (lane & 3) * 2;
            const float b0 = bias[c0], b1 = bias[c0 + 1];
            float2 o0 = make_float2(acc[mt][nt][0] + b0, acc[mt][nt][1] + b1);
            float2 o1 = make_float2(acc[mt][nt][2] + b0, acc[mt][nt][3] + b1);
            *(float2*)&C[(size_t)r0 * DM + c0]       = o0;
            *(float2*)&C[(size_t)(r0 + 8) * DM + c0] = o1;
        }
    }
}

/* ------------------------------------------------------------------ */
/* down[bh][c][s] = (q_down[c, h*64+:]*scale) . k_d[s,b,h*64+:]        */
/* ------------------------------------------------------------------ */
__global__ __launch_bounds__(128) void down_kernel(
    const float* __restrict__ q_down, const float* __restrict__ kd,
    float* __restrict__ down)
{
    const int bh = blockIdx.y;
    const int b  = bh >> 4;
    const int h  = bh & 15;
    const int s  = blockIdx.x * 128 + threadIdx.x;

    __shared__ float qd[CC][DH];
    for (int i = threadIdx.x; i < CC * DH; i += 128) {
        int c = i >> 6, d = i & 63;
        qd[c][d] = q_down[c * DM + h * DH + d] * QSCALE;
    }
    __syncthreads();

    const float* kp = kd + (size_t)s * (BATCH * DM) + b * DM + h * DH;
    float kr[DH];
    #pragma unroll
    for (int d = 0; d < DH; d++) kr[d] = kp[d];

    #pragma unroll 4
    for (int c = 0; c < CC; c++) {
        float acc = 0.f;
        #pragma unroll
        for (int d = 0; d < DH; d++) acc += qd[c][d] * kr[d];
        down[((size_t)bh * CC + c) * S_LEN + s] = acc;
    }
}

/* ------------------------------------------------------------------ */
__global__ __launch_bounds__(128) void maxexp_kernel(
    const float* __restrict__ down, float* __restrict__ wmat)
{
    const int bc = blockIdx.x;
    const int bh = bc >> 5;
    const int c  = bc & 31;
    const int t  = threadIdx.x;
    const float* row = down + (size_t)bc * S_LEN;

    float mx = -3.0e38f;
    for (int i = t; i < S_LEN; i += 128) mx = fmaxf(mx, row[i]);

    __shared__ float red[128];
    red[t] = mx;
    __syncthreads();
    for (int st = 64; st > 0; st >>= 1) {
        if (t < st) red[t] = fmaxf(red[t], red[t + st]);
        __syncthreads();
    }
    mx = red[0];

    for (int i = t; i < S_LEN; i += 128)
        wmat[((size_t)bh * S_LEN + i) * CC + c] = __expf(row[i] - mx);
}

/* ------------------------------------------------------------------ */
/* P1: per-(bh,chunk) totals.                                          */
/* ------------------------------------------------------------------ */
__global__ __launch_bounds__(256) void chunk_sum_kernel(
    const float* __restrict__ vk, const float* __restrict__ vv,
    const float* __restrict__ wmat,
    float* __restrict__ stK, float* __restrict__ stV, float* __restrict__ stN)
{
    const int bc = blockIdx.x;
    const int bh = bc >> 4, ch = bc & 15;
    const int b  = bh >> 4, h = bh & 15;
    const int tid = threadIdx.x, lane = tid & 31, warp = tid >> 5;

    __shared__ float vks[32][DH];
    __shared__ float vvs[32][DH];
    __shared__ float ws[32][CC];

    float Ak[8], Av[8];
    #pragma unroll
    for (int j = 0; j < 8; j++) { Ak[j] = 0.f; Av[j] = 0.f; }
    float norm = 0.f;
    const size_t base_off = (size_t)b * DM + h * DH;

    for (int sub = 0; sub < 2; sub++) {
        const int s0 = ch * CS + sub * 32;
        __syncthreads();
        for (int i = tid; i < 32 * DH; i += 256) {
            int r = i >> 6, d = i & 63;
            size_t g = (size_t)(s0 + r) * (BATCH * DM) + base_off + d;
            vks[r][d] = vk[g];
            vvs[r][d] = vv[g];
        }
        for (int i = tid; i < 32 * CC; i += 256) {
            int r = i >> 5, c = i & 31;
            ws[r][c] = wmat[((size_t)bh * S_LEN + s0 + r) * CC + c];
        }
        __syncthreads();
        for (int i = 0; i < 32; i++) {
            const float wvv = ws[i][lane];
            norm += wvv;
            #pragma unroll
            for (int j = 0; j < 8; j++) {
                Ak[j] += wvv * vks[i][warp * 8 + j];
                Av[j] += wvv * vvs[i][warp * 8 + j];
            }
        }
    }

    const size_t so = ((size_t)bh * NCH + ch) * 2048 + lane * 64 + warp * 8;
    #pragma unroll
    for (int j = 0; j < 8; j++) { stK[so + j] = Ak[j]; stV[so + j] = Av[j]; }
    if (warp == 0) stN[((size_t)bh * NCH + ch) * 32 + lane] = norm;
}

/* ------------------------------------------------------------------ */
__global__ __launch_bounds__(256) void scan_kernel(
    float* __restrict__ stK, float* __restrict__ stV, float* __restrict__ stN)
{
    const int bh = blockIdx.x, tid = threadIdx.x;
    float* bK = stK + (size_t)bh * NCH * 2048;
    float* bV = stV + (size_t)bh * NCH * 2048;
    for (int idx = tid; idx < 2048; idx += 256) {
        float a = 0.f;
        #pragma unroll
        for (int j = 0; j < NCH; j++) {
            float t = bK[j * 2048 + idx]; bK[j * 2048 + idx] = a; a += t;
        }
        a = 0.f;
        #pragma unroll
        for (int j = 0; j < NCH; j++) {
            float t = bV[j * 2048 + idx]; bV[j * 2048 + idx] = a; a += t;
        }
    }
    if (tid < 32) {
        float* bN = stN + (size_t)bh * NCH * 32;
        float a = 0.f;
        #pragma unroll
        for (int j = 0; j < NCH; j++) {
            float t = bN[j * 32 + tid]; bN[j * 32 + tid] = a; a += t;
        }
    }
}

/* ------------------------------------------------------------------ */
__global__ __launch_bounds__(256) void attn_out_kernel(
    const float* __restrict__ qu, const float* __restrict__ vk,
    const float* __restrict__ vv, const float* __restrict__ wmat,
    const float* __restrict__ stK, const float* __restrict__ stV,
    const float* __restrict__ stN, float* __restrict__ att)
{
    const int bc = blockIdx.x;
    const int bh = bc >> 4, ch = bc & 15;
    const int b  = bh >> 4, h = bh & 15;
    const int tid = threadIdx.x, lane = tid & 31, warp = tid >> 5;

    __shared__ float qs[32][DH];
    __shared__ float vks[32][DH];
    __shared__ float vvs[32][DH];
    __shared__ float ws[32][CC];
    __shared__ float part[2][8][32];

    const size_t so = ((size_t)bh * NCH + ch) * 2048 + lane * 64 + warp * 8;
    float Ak[8], Av[8];
    #pragma unroll
    for (int j = 0; j < 8; j++) { Ak[j] = stK[so + j]; Av[j] = stV[so + j]; }
    float norm = stN[((size_t)bh * NCH + ch) * 32 + lane];
    int buf = 0;

    const size_t base_off = (size_t)b * DM + h * DH;

    for (int sub = 0; sub < 2; sub++) {
        const int s0 = ch * CS + sub * 32;
        __syncthreads();
        for (int i = tid; i < 32 * DH; i += 256) {
            int r = i >> 6, d = i & 63;
            size_t g = (size_t)(s0 + r) * (BATCH * DM) + base_off + d;
            qs[r][d]  = qu[g] * QSCALE;
            vks[r][d] = vk[g];
            vvs[r][d] = vv[g];
        }
        for (int i = tid; i < 32 * CC; i += 256) {
            int r = i >> 5, c = i & 31;
            ws[r][c] = wmat[((size_t)bh * S_LEN + s0 + r) * CC + c];
        }
        __syncthreads();

        for (int i = 0; i < 32; i++) {
            const float wvv = ws[i][lane];
            norm += wvv;
            float up_part = 0.f;
            #pragma unroll
            for (int j = 0; j < 8; j++) {
                Ak[j] += wvv * vks[i][warp * 8 + j];
                Av[j] += wvv * vvs[i][warp * 8 + j];
                up_part += qs[i][warp * 8 + j] * Ak[j];
            }
            part[buf][warp][lane] = up_part;
            __syncthreads();

            float up = 0.f;
            #pragma unroll
            for (int ww = 0; ww < 8; ww++) up += part[buf][ww][lane];
            up /= norm;

            float mx = up;
            #pragma unroll
            for (int off = 16; off > 0; off >>= 1)
                mx = fmaxf(mx, __shfl_xor_sync(0xFFFFFFFFu, mx, off));
            float e = __expf(up - mx);
            float se = e;
            #pragma unroll
            for (int off = 16; off > 0; off >>= 1)
                se += __shfl_xor_sync(0xFFFFFFFFu, se, off);
            const float coeff = e / (se * norm);

            float o[8];
            #pragma unroll
            for (int j = 0; j < 8; j++) o[j] = coeff * Av[j];
            #pragma unroll
            for (int off = 16; off > 0; off >>= 1)
                #pragma unroll
                for (int j = 0; j < 8; j++)
                    o[j] += __shfl_xor_sync(0xFFFFFFFFu, o[j], off);

            if (lane < 8)
                att[(size_t)(s0 + i) * (BATCH * DM) + base_off + warp * 8 + lane] = o[lane];
            buf ^= 1;
        }
    }
}

/* ------------------------------------------------------------------ */
extern "C" void kernel_launch(void* const* d_in, const int* in_sizes, int n_in,
                              void* d_out, int out_size)
{
    (void)in_sizes; (void)n_in; (void)out_size;
    const float* x      = (const float*)d_in[0];
    const float* q_down = (const float*)d_in[1];
    const float* Wq     = (const float*)d_in[2];
    const float* bq     = (const float*)d_in[3];
    const float* Wk     = (const float*)d_in[4];
    const float* bk     = (const float*)d_in[5];
    const float* Wv     = (const float*)d_in[6];
    const float* bv     = (const float*)d_in[7];
    const float* Wo     = (const float*)d_in[8];
    const float* bo     = (const float*)d_in[9];
    float* out = (float*)d_out;

    float* scr = nullptr;
    cudaGetSymbolAddress((void**)&scr, g_scratch);
    float* g_qu  = scr + OFF_QU;
    float* g_kd  = scr + OFF_KD;
    float* g_vd  = scr + OFF_VD;
    float* g_vdk = scr + OFF_VDK;
    float* g_vdv = scr + OFF_VDV;
    float* g_att = scr + OFF_ATT;
    float* g_dn  = scr + OFF_DOWN;
    float* g_w   = scr + OFF_W;
    float* g_stk = scr + OFF_STK;
    float* g_stv = scr + OFF_STV;
    float* g_stn = scr + OFF_STN;

    __nv_bfloat16* xh  = (__nv_bfloat16*)(scr + OFF_XH);
    __nv_bfloat16* xl  = (__nv_bfloat16*)(scr + OFF_XL);
    __nv_bfloat16* wqh = (__nv_bfloat16*)(scr + OFF_WQH);
    __nv_bfloat16* wql = (__nv_bfloat16*)(scr + OFF_WQL);
    __nv_bfloat16* wkh = (__nv_bfloat16*)(scr + OFF_WKH);
    __nv_bfloat16* wkl = (__nv_bfloat16*)(scr + OFF_WKL);
    __nv_bfloat16* wvh = (__nv_bfloat16*)(scr + OFF_WVH);
    __nv_bfloat16* wvl = (__nv_bfloat16*)(scr + OFF_WVL);
    __nv_bfloat16* woh = (__nv_bfloat16*)(scr + OFF_WOH);
    __nv_bfloat16* wol = (__nv_bfloat16*)(scr + OFF_WOL);
    __nv_bfloat16* vdh = (__nv_bfloat16*)(scr + OFF_VDH);
    __nv_bfloat16* vdl = (__nv_bfloat16*)(scr + OFF_VDL);
    __nv_bfloat16* ath = (__nv_bfloat16*)(scr + OFF_ATH);
    __nv_bfloat16* atl = (__nv_bfloat16*)(scr + OFF_ATL);

    cudaFuncSetAttribute(gemm_bf16_bias,
                         cudaFuncAttributeMaxDynamicSharedMemorySize, GEMM_SMEM);

    const int n4x = MROWS * DM / 4;   /* 524288 */
    const int n4w = DM * DM / 4;      /* 262144 */

    cvt_split_kernel<<<n4x/256, 256>>>((const float4*)x,  (uint2*)xh,  (uint2*)xl,  n4x);
    cvt_split_kernel<<<n4w/256, 256>>>((const float4*)Wq, (uint2*)wqh, (uint2*)wql, n4w);
    cvt_split_kernel<<<n4w/256, 256>>>((const float4*)Wk, (uint2*)wkh, (uint2*)wkl, n4w);
    cvt_split_kernel<<<n4w/256, 256>>>((const float4*)Wv, (uint2*)wvh, (uint2*)wvl, n4w);
    cvt_split_kernel<<<n4w/256, 256>>>((const float4*)Wo, (uint2*)woh, (uint2*)wol, n4w);

    GemmArgs aq = {wqh, wql, bq, g_qu};
    GemmArgs ak = {wkh, wkl, bk, g_kd};
    GemmArgs av = {wvh, wvl, bv, g_vd};
    GemmArgs a2k = {wkh, wkl, bk, g_vdk};
    GemmArgs a2v = {wvh, wvl, bv, g_vdv};
    GemmArgs ao = {woh, wol, bo, out};

    /* fused QKV: grid.z = 3 */
    gemm_bf16_bias<<<dim3(DM/128, MROWS/128, 3), 256, GEMM_SMEM>>>(xh, xl, aq, ak, av);

    cvt_split_kernel<<<n4x/256, 256>>>((const float4*)g_vd, (uint2*)vdh, (uint2*)vdl, n4x);

    /* fused v_d_k / v_d_v: grid.z = 2 */
    gemm_bf16_bias<<<dim3(DM/128, MROWS/128, 2), 256, GEMM_SMEM>>>(vdh, vdl, a2k, a2v, a2v);

    down_kernel<<<dim3(S_LEN / 128, BATCH * NH), 128>>>(q_down, g_kd, g_dn);
    maxexp_kernel<<<BATCH * NH * CC, 128>>>(g_dn, g_w);

    chunk_sum_kernel<<<BATCH * NH * NCH, 256>>>(g_vdk, g_vdv, g_w,
                                                g_stk, g_stv, g_stn);
    scan_kernel<<<BATCH * NH, 256>>>(g_stk, g_stv, g_stn);
    attn_out_kernel<<<BATCH * NH * NCH, 256>>>(g_qu, g_vdk, g_vdv, g_w,
                                               g_stk, g_stv, g_stn, g_att);

    cvt_split_kernel<<<n4x/256, 256>>>((const float4*)g_att, (uint2*)ath, (uint2*)atl, n4x);

    gemm_bf16_bias<<<dim3(DM/128, MROWS/128, 1), 256, GEMM_SMEM>>>(ath, atl, ao, ao, ao);
}

// round 12
// speedup vs baseline: 3.9953x; 1.2325x over previous
#include <cuda_runtime.h>
#include <cuda_bf16.h>
#include <math.h>
#include <stdint.h>

#define S_LEN 1024
#define BATCH 2
#define DM    1024
#define NH    16
#define DH    64
#define CC    32
#define MROWS (S_LEN*BATCH)
#define QSCALE 0.125f
#define NCH   32
#define CS    32

/* ------------------------------------------------------------------ */
/* Scratch: 29M floats = 116 MB.                                       */
/* ------------------------------------------------------------------ */
__device__ float g_scratch[29 * 1024 * 1024];

#define MB (1024*1024)
#define OFF_QU   ((size_t)0)
#define OFF_KD   ((size_t)2*MB)
#define OFF_VD   ((size_t)4*MB)
#define OFF_VDK  ((size_t)6*MB)
#define OFF_VDV  ((size_t)8*MB)
#define OFF_ATT  ((size_t)10*MB)
#define OFF_DOWN ((size_t)12*MB)
#define OFF_W    ((size_t)13*MB)
#define OFF_STK  ((size_t)14*MB)          /* 2M  [bh][ch][c][d] */
#define OFF_STV  ((size_t)16*MB)          /* 2M */
#define OFF_STN  ((size_t)18*MB)          /* 32K */
#define OFF_XH   ((size_t)19*MB)
#define OFF_XL   ((size_t)20*MB)
#define OFF_WQH  ((size_t)21*MB)
#define OFF_WQL  ((size_t)(21*MB+MB/2))
#define OFF_WKH  ((size_t)22*MB)
#define OFF_WKL  ((size_t)(22*MB+MB/2))
#define OFF_WVH  ((size_t)23*MB)
#define OFF_WVL  ((size_t)(23*MB+MB/2))
#define OFF_WOH  ((size_t)24*MB)
#define OFF_WOL  ((size_t)(24*MB+MB/2))
#define OFF_VDH  ((size_t)25*MB)
#define OFF_VDL  ((size_t)26*MB)
#define OFF_ATH  ((size_t)27*MB)
#define OFF_ATL  ((size_t)28*MB)

/* ================================================================== */
/* helpers                                                             */
/* ================================================================== */
__device__ __forceinline__ uint32_t smem_addr_u32(const void* p) {
    uint32_t a;
    asm("{ .reg .u64 t; cvta.to.shared.u64 t, %1; cvt.u32.u64 %0, t; }"
        : "=r"(a) : "l"(p));
    return a;
}

#define LDM4(r, addr)                                                         \
    asm volatile("ldmatrix.sync.aligned.m8n8.x4.shared.b16 {%0,%1,%2,%3}, [%4];" \
        : "=r"((r)[0]), "=r"((r)[1]), "=r"((r)[2]), "=r"((r)[3])              \
        : "r"(addr))

#define MMA16816(d, a, b0, b1)                                                \
    asm volatile(                                                             \
        "mma.sync.aligned.m16n8k16.row.col.f32.bf16.bf16.f32 "                \
        "{%0,%1,%2,%3}, {%4,%5,%6,%7}, {%8,%9}, {%0,%1,%2,%3};"               \
        : "+f"((d)[0]), "+f"((d)[1]), "+f"((d)[2]), "+f"((d)[3])              \
        : "r"((a)[0]), "r"((a)[1]), "r"((a)[2]), "r"((a)[3]),                 \
          "r"(b0), "r"(b1))

#define CP16(dst, src)                                                        \
    asm volatile("cp.async.cg.shared.global [%0], [%1], 16;"                  \
        :: "r"(dst), "l"((size_t)__cvta_generic_to_global(src)) : "memory")
#define CP_COMMIT() asm volatile("cp.async.commit_group;" ::: "memory")
#define CP_WAIT2()  asm volatile("cp.async.wait_group 2;"  ::: "memory")

__device__ __forceinline__ uint32_t pack_bf16(float x, float y) {
    __nv_bfloat16 a = __float2bfloat16(x), b = __float2bfloat16(y);
    return (uint32_t)__bfloat16_as_ushort(a) |
           ((uint32_t)__bfloat16_as_ushort(b) << 16);
}

/* ================================================================== */
/* fp32 -> (hi, lo) bf16 planes                                        */
/* ================================================================== */
__device__ __forceinline__ void cvt_body(const float4* src, uint2* hi,
                                         uint2* lo, int i)
{
    float4 v = src[i];
    __nv_bfloat16 a = __float2bfloat16(v.x), b = __float2bfloat16(v.y),
                  c = __float2bfloat16(v.z), d = __float2bfloat16(v.w);
    uint2 h, l;
    h.x = (uint32_t)__bfloat16_as_ushort(a) | ((uint32_t)__bfloat16_as_ushort(b) << 16);
    h.y = (uint32_t)__bfloat16_as_ushort(c) | ((uint32_t)__bfloat16_as_ushort(d) << 16);
    l.x = pack_bf16(v.x - __bfloat162float(a), v.y - __bfloat162float(b));
    l.y = pack_bf16(v.z - __bfloat162float(c), v.w - __bfloat162float(d));
    hi[i] = h;
    lo[i] = l;
}

__global__ __launch_bounds__(256) void cvt_split_kernel(
    const float4* __restrict__ src, uint2* __restrict__ hi,
    uint2* __restrict__ lo, int n4)
{
    int i = blockIdx.x * 256 + threadIdx.x;
    if (i < n4) cvt_body(src, hi, lo, i);
}

struct CvtSeg { const float4* src; uint2* hi; uint2* lo; int n4; };

__global__ __launch_bounds__(256) void cvt_multi_kernel(
    CvtSeg s0, CvtSeg s1, CvtSeg s2, CvtSeg s3, CvtSeg s4)
{
    CvtSeg s = (blockIdx.y == 0) ? s0 : (blockIdx.y == 1) ? s1 :
               (blockIdx.y == 2) ? s2 : (blockIdx.y == 3) ? s3 : s4;
    int i = blockIdx.x * 256 + threadIdx.x;
    if (i < s.n4) cvt_body(s.src, s.hi, s.lo, i);
}

/* ================================================================== */
/* HMMA GEMM NT + bias, bf16 hi/lo, cp.async 4-stage, 512 threads.     */
/* 128x128 tile, 16 warps (32x32 each), product-major MMA order.       */
/* ================================================================== */
#define RS      80
#define PART_B  (128*RS)
#define STG_B   (4*PART_B)
#define NSTAGE  4
#define GEMM_SMEM (NSTAGE*STG_B)   /* 163840 */

struct GemmArgs {
    const __nv_bfloat16* Bh;
    const __nv_bfloat16* Bl;
    const float*         bias;
    float*               C;
};

__device__ __forceinline__ void issue_stage(
    uint32_t sdst, const __nv_bfloat16* Ah, const __nv_bfloat16* Al,
    const __nv_bfloat16* Bh, const __nv_bfloat16* Bl,
    int bm, int bn, int k0, int tid)
{
    const int r = tid >> 2, seg = tid & 3;
    const size_t ga = (size_t)(bm + r) * DM + k0 + seg * 8;
    const size_t gb = (size_t)(bn + r) * DM + k0 + seg * 8;
    const uint32_t d = sdst + (uint32_t)(r * RS + seg * 16);
    CP16(d,            Ah + ga);
    CP16(d + PART_B,   Al + ga);
    CP16(d + 2*PART_B, Bh + gb);
    CP16(d + 3*PART_B, Bl + gb);
}

__global__ __launch_bounds__(512, 1) void gemm_bf16_bias(
    const __nv_bfloat16* __restrict__ Ah, const __nv_bfloat16* __restrict__ Al,
    GemmArgs a0, GemmArgs a1, GemmArgs a2)
{
    extern __shared__ __align__(16) char sm[];
    const uint32_t sbase = smem_addr_u32(sm);
    const int tid = threadIdx.x, lane = tid & 31, w = tid >> 5;
    const int wm = w & 3, wn = w >> 2;           /* 4x4 warp grid */
    const int bm = blockIdx.y * 128, bn = blockIdx.x * 128;
    const GemmArgs ar = (blockIdx.z == 0) ? a0 : (blockIdx.z == 1) ? a1 : a2;
    const __nv_bfloat16* Bh = ar.Bh;
    const __nv_bfloat16* Bl = ar.Bl;

    float acc[2][4][4];
    #pragma unroll
    for (int i = 0; i < 2; i++)
        #pragma unroll
        for (int j = 0; j < 4; j++)
            #pragma unroll
            for (int k = 0; k < 4; k++) acc[i][j][k] = 0.f;

    const uint32_t aRel = (uint32_t)((wm * 32 + (lane & 15)) * RS + (lane >> 4) * 16);
    const uint32_t bRel = (uint32_t)((wn * 32 + (lane & 7) + ((lane >> 4) & 1) * 8) * RS
                                     + ((lane >> 3) & 1) * 16);

    #pragma unroll
    for (int s = 0; s < 3; s++) {
        issue_stage(sbase + s * STG_B, Ah, Al, Bh, Bl, bm, bn, s * 32, tid);
        CP_COMMIT();
    }

    for (int kt = 0; kt < 32; ++kt) {
        CP_WAIT2();
        __syncthreads();

        if (kt + 3 < 32)
            issue_stage(sbase + ((kt + 3) & 3) * STG_B, Ah, Al, Bh, Bl,
                        bm, bn, (kt + 3) * 32, tid);
        CP_COMMIT();

        const uint32_t so = sbase + (uint32_t)(kt & 3) * STG_B;
        #pragma unroll
        for (int ks = 0; ks < 2; ++ks) {
            uint32_t ah[2][4], al[2][4], bh[2][4], bl[2][4];
            #pragma unroll
            for (int mt = 0; mt < 2; mt++) {
                const uint32_t off = aRel + (uint32_t)(mt * 16 * RS + ks * 32);
                LDM4(ah[mt], so + off);
                LDM4(al[mt], so + PART_B + off);
            }
            #pragma unroll
            for (int g = 0; g < 2; g++) {
                const uint32_t off = bRel + (uint32_t)(g * 16 * RS + ks * 32);
                LDM4(bh[g], so + 2*PART_B + off);
                LDM4(bl[g], so + 3*PART_B + off);
            }
            /* product-major: 8 independent accs between reuse */
            #pragma unroll
            for (int mt = 0; mt < 2; mt++)
                #pragma unroll
                for (int nt = 0; nt < 4; nt++) {
                    const int g = nt >> 1, p = (nt & 1) * 2;
                    MMA16816(acc[mt][nt], ah[mt], bh[g][p], bh[g][p + 1]);
                }
            #pragma unroll
            for (int mt = 0; mt < 2; mt++)
                #pragma unroll
                for (int nt = 0; nt < 4; nt++) {
                    const int g = nt >> 1, p = (nt & 1) * 2;
                    MMA16816(acc[mt][nt], al[mt], bh[g][p], bh[g][p + 1]);
                }
            #pragma unroll
            for (int mt = 0; mt < 2; mt++)
                #pragma unroll
                for (int nt = 0; nt < 4; nt++) {
                    const int g = nt >> 1, p = (nt & 1) * 2;
                    MMA16816(acc[mt][nt], ah[mt], bl[g][p], bl[g][p + 1]);
                }
        }
    }

    float* C = ar.C;
    const float* bias = ar.bias;
    #pragma unroll
    for (int mt = 0; mt < 2; mt++) {
        const int r0 = bm + wm * 32 + mt * 16 + (lane >> 2);
        #pragma unroll
        for (int nt = 0; nt < 4; nt++) {
            const int c0 = bn + wn * 32 + nt * 8 + (lane & 3) * 2;
            const float b0 = bias[c0], b1 = bias[c0 + 1];
            float2 o0 = make_float2(acc[mt][nt][0] + b0, acc[mt][nt][1] + b1);
            float2 o1 = make_float2(acc[mt][nt][2] + b0, acc[mt][nt][3] + b1);
            *(float2*)&C[(size_t)r0 * DM + c0]       = o0;
            *(float2*)&C[(size_t)(r0 + 8) * DM + c0] = o1;
        }
    }
}

/* ------------------------------------------------------------------ */
__global__ __launch_bounds__(128) void down_kernel(
    const float* __restrict__ q_down, const float* __restrict__ kd,
    float* __restrict__ down)
{
    const int bh = blockIdx.y;
    const int b  = bh >> 4;
    const int h  = bh & 15;
    const int s  = blockIdx.x * 128 + threadIdx.x;

    __shared__ float qd[CC][DH];
    for (int i = threadIdx.x; i < CC * DH; i += 128) {
        int c = i >> 6, d = i & 63;
        qd[c][d] = q_down[c * DM + h * DH + d] * QSCALE;
    }
    __syncthreads();

    const float* kp = kd + (size_t)s * (BATCH * DM) + b * DM + h * DH;
    float kr[DH];
    #pragma unroll
    for (int d = 0; d < DH; d++) kr[d] = kp[d];

    #pragma unroll 4
    for (int c = 0; c < CC; c++) {
        float acc = 0.f;
        #pragma unroll
        for (int d = 0; d < DH; d++) acc += qd[c][d] * kr[d];
        down[((size_t)bh * CC + c) * S_LEN + s] = acc;
    }
}

/* ------------------------------------------------------------------ */
__global__ __launch_bounds__(128) void maxexp_kernel(
    const float* __restrict__ down, float* __restrict__ wmat)
{
    const int bc = blockIdx.x;
    const int bh = bc >> 5;
    const int c  = bc & 31;
    const int t  = threadIdx.x;
    const float* row = down + (size_t)bc * S_LEN;

    float mx = -3.0e38f;
    for (int i = t; i < S_LEN; i += 128) mx = fmaxf(mx, row[i]);

    __shared__ float red[128];
    red[t] = mx;
    __syncthreads();
    for (int st = 64; st > 0; st >>= 1) {
        if (t < st) red[t] = fmaxf(red[t], red[t + st]);
        __syncthreads();
    }
    mx = red[0];

    for (int i = t; i < S_LEN; i += 128)
        wmat[((size_t)bh * S_LEN + i) * CC + c] = __expf(row[i] - mx);
}

/* ------------------------------------------------------------------ */
/* P1: per-(bh,chunk CS=32) totals.                                    */
/* ------------------------------------------------------------------ */
__global__ __launch_bounds__(256) void chunk_sum_kernel(
    const float* __restrict__ vk, const float* __restrict__ vv,
    const float* __restrict__ wmat,
    float* __restrict__ stK, float* __restrict__ stV, float* __restrict__ stN)
{
    const int bc = blockIdx.x;
    const int bh = bc >> 5, ch = bc & 31;
    const int b  = bh >> 4, h = bh & 15;
    const int tid = threadIdx.x, lane = tid & 31, warp = tid >> 5;
    const int s0 = ch * CS;

    __shared__ float vks[CS][DH];
    __shared__ float vvs[CS][DH];
    __shared__ float ws[CS][CC];

    const size_t base_off = (size_t)b * DM + h * DH;

    for (int i = tid; i < CS * DH; i += 256) {
        int r = i >> 6, d = i & 63;
        size_t g = (size_t)(s0 + r) * (BATCH * DM) + base_off + d;
        vks[r][d] = vk[g];
        vvs[r][d] = vv[g];
    }
    for (int i = tid; i < CS * CC; i += 256) {
        int r = i >> 5, c = i & 31;
        ws[r][c] = wmat[((size_t)bh * S_LEN + s0 + r) * CC + c];
    }
    __syncthreads();

    float Ak[8], Av[8];
    #pragma unroll
    for (int j = 0; j < 8; j++) { Ak[j] = 0.f; Av[j] = 0.f; }
    float norm = 0.f;
    for (int i = 0; i < CS; i++) {
        const float wvv = ws[i][lane];
        norm += wvv;
        #pragma unroll
        for (int j = 0; j < 8; j++) {
            Ak[j] += wvv * vks[i][warp * 8 + j];
            Av[j] += wvv * vvs[i][warp * 8 + j];
        }
    }

    const size_t so = ((size_t)bh * NCH + ch) * 2048 + lane * 64 + warp * 8;
    #pragma unroll
    for (int j = 0; j < 8; j++) { stK[so + j] = Ak[j]; stV[so + j] = Av[j]; }
    if (warp == 0) stN[((size_t)bh * NCH + ch) * 32 + lane] = norm;
}

/* ------------------------------------------------------------------ */
__global__ __launch_bounds__(256) void scan_kernel(
    float* __restrict__ stK, float* __restrict__ stV, float* __restrict__ stN)
{
    const int bh = blockIdx.x, tid = threadIdx.x;
    float* bK = stK + (size_t)bh * NCH * 2048;
    float* bV = stV + (size_t)bh * NCH * 2048;
    for (int idx = tid; idx < 2048; idx += 256) {
        float a = 0.f;
        #pragma unroll
        for (int j = 0; j < NCH; j++) {
            float t = bK[j * 2048 + idx]; bK[j * 2048 + idx] = a; a += t;
        }
        a = 0.f;
        #pragma unroll
        for (int j = 0; j < NCH; j++) {
            float t = bV[j * 2048 + idx]; bV[j * 2048 + idx] = a; a += t;
        }
    }
    if (tid < 32) {
        float* bN = stN + (size_t)bh * NCH * 32;
        float a = 0.f;
        #pragma unroll
        for (int j = 0; j < NCH; j++) {
            float t = bN[j * 32 + tid]; bN[j * 32 + tid] = a; a += t;
        }
    }
}

/* ------------------------------------------------------------------ */
/* P3: chunked attention as masked small GEMMs. One block/(bh,ch).     */
/*  P = Q·VK^T (mask t<=s);  up = (Q·Ak0^T + P·w)/ncum;  softmax;     */
/*  G = coeff·w^T (mask);   out = coeff·Av0 + G·VV.                    */
/* ------------------------------------------------------------------ */
#define CPAD 33
#define DPAD 65
#define ACH_SMEM ((5*32*DPAD + 4*32*CPAD + 32) * 4)   /* 58624 B */

__global__ __launch_bounds__(256) void attn_chunk_kernel(
    const float* __restrict__ qu, const float* __restrict__ vkm,
    const float* __restrict__ vvm, const float* __restrict__ wmat,
    const float* __restrict__ stK, const float* __restrict__ stV,
    const float* __restrict__ stN, float* __restrict__ att)
{
    extern __shared__ float sh[];
    float* Q  = sh;
    float* VK = sh + 32*DPAD;
    float* VV = sh + 2*32*DPAD;
    float* AK = sh + 3*32*DPAD;
    float* AV = sh + 4*32*DPAD;
    float* P  = sh + 5*32*DPAD;               /* later reused for G */
    float* W  = sh + 5*32*DPAD + 32*CPAD;
    float* C  = sh + 5*32*DPAD + 2*32*CPAD;
    float* NC = sh + 5*32*DPAD + 3*32*CPAD;
    float* N0 = sh + 5*32*DPAD + 4*32*CPAD;

    const int bc = blockIdx.x, bh = bc >> 5, ch = bc & 31;
    const int b = bh >> 4, h = bh & 15;
    const int tid = threadIdx.x;
    const int s0 = ch * CS;
    const size_t base = (size_t)b * DM + h * DH;

    for (int i = tid; i < 32 * 64; i += 256) {
        int r = i >> 6, d = i & 63;
        size_t g = (size_t)(s0 + r) * (BATCH * DM) + base + d;
        Q[r * DPAD + d]  = qu[g] * QSCALE;
        VK[r * DPAD + d] = vkm[g];
        VV[r * DPAD + d] = vvm[g];
    }
    const size_t st0 = ((size_t)bh * NCH + ch) * 2048;
    for (int i = tid; i < 32 * 64; i += 256) {
        int c = i >> 6, d = i & 63;
        AK[c * DPAD + d] = stK[st0 + i];
        AV[c * DPAD + d] = stV[st0 + i];
    }
    for (int i = tid; i < 32 * 32; i += 256) {
        int r = i >> 5, c = i & 31;
        W[r * CPAD + c] = wmat[((size_t)bh * S_LEN + s0 + r) * CC + c];
    }
    if (tid < 32) N0[tid] = stN[((size_t)bh * NCH + ch) * 32 + tid];
    __syncthreads();

    /* ncum (inclusive) — 32 threads, serial s; no one reads it yet */
    if (tid < 32) {
        float run = N0[tid];
        for (int s = 0; s < 32; s++) {
            run += W[s * CPAD + tid];
            NC[s * CPAD + tid] = run;
        }
    }

    /* M1: P = Q·VK^T, mask t<=s */
    {
        const int ts = (tid >> 4) * 2, tt = (tid & 15) * 2;
        float c00 = 0, c01 = 0, c10 = 0, c11 = 0;
        for (int d = 0; d < 64; d++) {
            float a0 = Q[ts * DPAD + d],      a1 = Q[(ts + 1) * DPAD + d];
            float b0 = VK[tt * DPAD + d],     b1 = VK[(tt + 1) * DPAD + d];
            c00 += a0 * b0; c01 += a0 * b1; c10 += a1 * b0; c11 += a1 * b1;
        }
        P[ts * CPAD + tt]           = (tt     <= ts)     ? c00 : 0.f;
        P[ts * CPAD + tt + 1]       = (tt + 1 <= ts)     ? c01 : 0.f;
        P[(ts + 1) * CPAD + tt]     = (tt     <= ts + 1) ? c10 : 0.f;
        P[(ts + 1) * CPAD + tt + 1] = (tt + 1 <= ts + 1) ? c11 : 0.f;
    }
    __syncthreads();

    /* M2+M3: up = (Q·AK^T + P·W)/NC */
    {
        const int ts = (tid >> 4) * 2, tc = (tid & 15) * 2;
        float c00 = 0, c01 = 0, c10 = 0, c11 = 0;
        for (int d = 0; d < 64; d++) {
            float a0 = Q[ts * DPAD + d],  a1 = Q[(ts + 1) * DPAD + d];
            float k0 = AK[tc * DPAD + d], k1 = AK[(tc + 1) * DPAD + d];
            c00 += a0 * k0; c01 += a0 * k1; c10 += a1 * k0; c11 += a1 * k1;
        }
        for (int t = 0; t < 32; t++) {
            float p0 = P[ts * CPAD + t], p1 = P[(ts + 1) * CPAD + t];
            float w0 = W[t * CPAD + tc], w1 = W[t * CPAD + tc + 1];
            c00 += p0 * w0; c01 += p0 * w1; c10 += p1 * w0; c11 += p1 * w1;
        }
        C[ts * CPAD + tc]           = c00 / NC[ts * CPAD + tc];
        C[ts * CPAD + tc + 1]       = c01 / NC[ts * CPAD + tc + 1];
        C[(ts + 1) * CPAD + tc]     = c10 / NC[(ts + 1) * CPAD + tc];
        C[(ts + 1) * CPAD + tc + 1] = c11 / NC[(ts + 1) * CPAD + tc + 1];
    }
    __syncthreads();

    /* softmax over c per row, then coeff = p/ncum */
    {
        const int lane = tid & 31, w = tid >> 5;
        #pragma unroll
        for (int r = w * 4; r < w * 4 + 4; r++) {
            float v = C[r * CPAD + lane];
            float mx = v;
            #pragma unroll
            for (int o = 16; o > 0; o >>= 1)
                mx = fmaxf(mx, __shfl_xor_sync(0xFFFFFFFFu, mx, o));
            float e = __expf(v - mx);
            float se = e;
            #pragma unroll
            for (int o = 16; o > 0; o >>= 1)
                se += __shfl_xor_sync(0xFFFFFFFFu, se, o);
            C[r * CPAD + lane] = e / (se * NC[r * CPAD + lane]);
        }
    }
    __syncthreads();

    /* M4: G = coeff·W^T, mask t<=s (into P) */
    {
        const int ts = (tid >> 4) * 2, tt = (tid & 15) * 2;
        float c00 = 0, c01 = 0, c10 = 0, c11 = 0;
        for (int c = 0; c < 32; c++) {
            float a0 = C[ts * CPAD + c], a1 = C[(ts + 1) * CPAD + c];
            float w0 = W[tt * CPAD + c], w1 = W[(tt + 1) * CPAD + c];
            c00 += a0 * w0; c01 += a0 * w1; c10 += a1 * w0; c11 += a1 * w1;
        }
        __syncthreads();   /* all P reads (M2) done; safe to overwrite */
        P[ts * CPAD + tt]           = (tt     <= ts)     ? c00 : 0.f;
        P[ts * CPAD + tt + 1]       = (tt + 1 <= ts)     ? c01 : 0.f;
        P[(ts + 1) * CPAD + tt]     = (tt     <= ts + 1) ? c10 : 0.f;
        P[(ts + 1) * CPAD + tt + 1] = (tt + 1 <= ts + 1) ? c11 : 0.f;
    }
    __syncthreads();

    /* M5: out = coeff·AV + G·VV */
    {
        const int sg = (tid >> 4) * 2, dg = (tid & 15) * 4;
        float acc[2][4] = {{0, 0, 0, 0}, {0, 0, 0, 0}};
        for (int c = 0; c < 32; c++) {
            float a0 = C[sg * CPAD + c], a1 = C[(sg + 1) * CPAD + c];
            #pragma unroll
            for (int j = 0; j < 4; j++) {
                float v = AV[c * DPAD + dg + j];
                acc[0][j] += a0 * v; acc[1][j] += a1 * v;
            }
        }
        for (int t = 0; t < 32; t++) {
            float g0 = P[sg * CPAD + t], g1 = P[(sg + 1) * CPAD + t];
            #pragma unroll
            for (int j = 0; j < 4; j++) {
                float v = VV[t * DPAD + dg + j];
                acc[0][j] += g0 * v; acc[1][j] += g1 * v;
            }
        }
        #pragma unroll
        for (int i = 0; i < 2; i++)
            #pragma unroll
            for (int j = 0; j < 4; j++)
                att[(size_t)(s0 + sg + i) * (BATCH * DM) + base + dg + j] = acc[i][j];
    }
}

/* ------------------------------------------------------------------ */
extern "C" void kernel_launch(void* const* d_in, const int* in_sizes, int n_in,
                              void* d_out, int out_size)
{
    (void)in_sizes; (void)n_in; (void)out_size;
    const float* x      = (const float*)d_in[0];
    const float* q_down = (const float*)d_in[1];
    const float* Wq     = (const float*)d_in[2];
    const float* bq     = (const float*)d_in[3];
    const float* Wk     = (const float*)d_in[4];
    const float* bk     = (const float*)d_in[5];
    const float* Wv     = (const float*)d_in[6];
    const float* bv     = (const float*)d_in[7];
    const float* Wo     = (const float*)d_in[8];
    const float* bo     = (const float*)d_in[9];
    float* out = (float*)d_out;

    float* scr = nullptr;
    cudaGetSymbolAddress((void**)&scr, g_scratch);
    float* g_qu  = scr + OFF_QU;
    float* g_kd  = scr + OFF_KD;
    float* g_vd  = scr + OFF_VD;
    float* g_vdk = scr + OFF_VDK;
    float* g_vdv = scr + OFF_VDV;
    float* g_att = scr + OFF_ATT;
    float* g_dn  = scr + OFF_DOWN;
    float* g_w   = scr + OFF_W;
    float* g_stk = scr + OFF_STK;
    float* g_stv = scr + OFF_STV;
    float* g_stn = scr + OFF_STN;

    __nv_bfloat16* xh  = (__nv_bfloat16*)(scr + OFF_XH);
    __nv_bfloat16* xl  = (__nv_bfloat16*)(scr + OFF_XL);
    __nv_bfloat16* wqh = (__nv_bfloat16*)(scr + OFF_WQH);
    __nv_bfloat16* wql = (__nv_bfloat16*)(scr + OFF_WQL);
    __nv_bfloat16* wkh = (__nv_bfloat16*)(scr + OFF_WKH);
    __nv_bfloat16* wkl = (__nv_bfloat16*)(scr + OFF_WKL);
    __nv_bfloat16* wvh = (__nv_bfloat16*)(scr + OFF_WVH);
    __nv_bfloat16* wvl = (__nv_bfloat16*)(scr + OFF_WVL);
    __nv_bfloat16* woh = (__nv_bfloat16*)(scr + OFF_WOH);
    __nv_bfloat16* wol = (__nv_bfloat16*)(scr + OFF_WOL);
    __nv_bfloat16* vdh = (__nv_bfloat16*)(scr + OFF_VDH);
    __nv_bfloat16* vdl = (__nv_bfloat16*)(scr + OFF_VDL);
    __nv_bfloat16* ath = (__nv_bfloat16*)(scr + OFF_ATH);
    __nv_bfloat16* atl = (__nv_bfloat16*)(scr + OFF_ATL);

    cudaFuncSetAttribute(gemm_bf16_bias,
                         cudaFuncAttributeMaxDynamicSharedMemorySize, GEMM_SMEM);
    cudaFuncSetAttribute(attn_chunk_kernel,
                         cudaFuncAttributeMaxDynamicSharedMemorySize, ACH_SMEM);

    const int n4x = MROWS * DM / 4;
    const int n4w = DM * DM / 4;

    /* fused conversions: x + 4 weights */
    CvtSeg cs0 = {(const float4*)x,  (uint2*)xh,  (uint2*)xl,  n4x};
    CvtSeg cs1 = {(const float4*)Wq, (uint2*)wqh, (uint2*)wql, n4w};
    CvtSeg cs2 = {(const float4*)Wk, (uint2*)wkh, (uint2*)wkl, n4w};
    CvtSeg cs3 = {(const float4*)Wv, (uint2*)wvh, (uint2*)wvl, n4w};
    CvtSeg cs4 = {(const float4*)Wo, (uint2*)woh, (uint2*)wol, n4w};
    cvt_multi_kernel<<<dim3(n4x / 256, 5), 256>>>(cs0, cs1, cs2, cs3, cs4);

    GemmArgs aq  = {wqh, wql, bq, g_qu};
    GemmArgs ak  = {wkh, wkl, bk, g_kd};
    GemmArgs av  = {wvh, wvl, bv, g_vd};
    GemmArgs a2k = {wkh, wkl, bk, g_vdk};
    GemmArgs a2v = {wvh, wvl, bv, g_vdv};
    GemmArgs ao  = {woh, wol, bo, out};

    gemm_bf16_bias<<<dim3(DM/128, MROWS/128, 3), 512, GEMM_SMEM>>>(xh, xl, aq, ak, av);

    cvt_split_kernel<<<n4x/256, 256>>>((const float4*)g_vd, (uint2*)vdh, (uint2*)vdl, n4x);

    gemm_bf16_bias<<<dim3(DM/128, MROWS/128, 2), 512, GEMM_SMEM>>>(vdh, vdl, a2k, a2v, a2v);

    down_kernel<<<dim3(S_LEN / 128, BATCH * NH), 128>>>(q_down, g_kd, g_dn);
    maxexp_kernel<<<BATCH * NH * CC, 128>>>(g_dn, g_w);

    chunk_sum_kernel<<<BATCH * NH * NCH, 256>>>(g_vdk, g_vdv, g_w,
                                                g_stk, g_stv, g_stn);
    scan_kernel<<<BATCH * NH, 256>>>(g_stk, g_stv, g_stn);
    attn_chunk_kernel<<<BATCH * NH * NCH, 256, ACH_SMEM>>>(
        g_qu, g_vdk, g_vdv, g_w, g_stk, g_stv, g_stn, g_att);

    cvt_split_kernel<<<n4x/256, 256>>>((const float4*)g_att, (uint2*)ath, (uint2*)atl, n4x);

    gemm_bf16_bias<<<dim3(DM/128, MROWS/128, 1), 512, GEMM_SMEM>>>(ath, atl, ao, ao, ao);
}